// round 9
// baseline (speedup 1.0000x reference)
#include <cuda_runtime.h>
#include <cuda_bf16.h>
#include <cstdint>

#define THREADS 128
#define NWARP 4
#define TILES_PER_WARP 2
#define NCOEF 1001

__device__ __forceinline__ uint32_t cvta_s(const void* p) {
    return (uint32_t)__cvta_generic_to_shared(p);
}
__device__ __forceinline__ void ldm_x4(uint32_t& r0, uint32_t& r1,
                                       uint32_t& r2, uint32_t& r3, uint32_t addr) {
    asm volatile("ldmatrix.sync.aligned.m8n8.x4.shared.b16 {%0,%1,%2,%3}, [%4];"
                 : "=r"(r0), "=r"(r1), "=r"(r2), "=r"(r3) : "r"(addr));
}
__device__ __forceinline__ void ldm_x2(uint32_t& r0, uint32_t& r1, uint32_t addr) {
    asm volatile("ldmatrix.sync.aligned.m8n8.x2.shared.b16 {%0,%1}, [%2];"
                 : "=r"(r0), "=r"(r1) : "r"(addr));
}
__device__ __forceinline__ void mma16816(float* d, const uint32_t* a,
                                         const uint32_t* b) {
    asm volatile("mma.sync.aligned.m16n8k16.row.col.f32.bf16.bf16.f32 "
                 "{%0,%1,%2,%3}, {%4,%5,%6,%7}, {%8,%9}, {%0,%1,%2,%3};"
                 : "+f"(d[0]), "+f"(d[1]), "+f"(d[2]), "+f"(d[3])
                 : "r"(a[0]), "r"(a[1]), "r"(a[2]), "r"(a[3]),
                   "r"(b[0]), "r"(b[1]));
}
// First accumulation: c = 0 (no D-init MOVs needed)
__device__ __forceinline__ void mma16816_z(float* d, const uint32_t* a,
                                           const uint32_t* b) {
    asm volatile("mma.sync.aligned.m16n8k16.row.col.f32.bf16.bf16.f32 "
                 "{%0,%1,%2,%3}, {%4,%5,%6,%7}, {%8,%9}, {%10,%10,%10,%10};"
                 : "=f"(d[0]), "=f"(d[1]), "=f"(d[2]), "=f"(d[3])
                 : "r"(a[0]), "r"(a[1]), "r"(a[2]), "r"(a[3]),
                   "r"(b[0]), "r"(b[1]), "f"(0.0f));
}

// Rows are 128B (64 bf16) = 8 chunks of 16B, XOR-swizzled:
//   addr(row, chunk) = base + row*128 + ((chunk ^ (row&7)) & 7)*16
// A tile (per warp, double-buffered): row = element, chunks 0-3 = p_hi,
//   chunks 4-7 = p_lo. W tile: row = group n, chunks 0-3 = w_hi, 4-7 = w_lo.

// Compute x^0..x^31 (power-of-2 factor tree, dep depth ~7 muls), bf16 hi/lo
// split, store into A buffer `abuf`. Returns q = x^32.
__device__ __forceinline__ float powers_store(float x, uint32_t abuf, int lane) {
    float x2 = x * x, x4 = x2 * x2, x8 = x4 * x4, x16 = x8 * x8;
    float e[16];
    e[0] = 1.0f;      e[1] = x2;        e[2] = x4;        e[3] = x4 * x2;
    e[4] = x8;        e[5] = x8 * x2;   e[6] = x8 * x4;   e[7] = e[6] * x2;
    e[8] = x16;       e[9] = x16 * x2;  e[10] = x16 * x4; e[11] = e[10] * x2;
    e[12] = x16 * x8; e[13] = e[12] * x2; e[14] = e[12] * x4; e[15] = e[14] * x2;

    uint32_t hi[16], lo[16];
    #pragma unroll
    for (int i = 0; i < 16; i++) {
        float p0 = e[i], p1 = e[i] * x;
        __nv_bfloat162 h2 = __floats2bfloat162_rn(p0, p1);    // low = p0
        uint32_t hb = *reinterpret_cast<uint32_t*>(&h2);
        float h0 = __uint_as_float(hb << 16);
        float h1 = __uint_as_float(hb & 0xFFFF0000u);
        __nv_bfloat162 l2 = __floats2bfloat162_rn(p0 - h0, p1 - h1);
        hi[i] = hb;
        lo[i] = *reinterpret_cast<uint32_t*>(&l2);
    }
    #pragma unroll
    for (int c = 0; c < 4; c++) {
        uint32_t ah = abuf + lane * 128 + ((c ^ (lane & 7)) & 7) * 16;
        uint32_t al = abuf + lane * 128 + (((c + 4) ^ (lane & 7)) & 7) * 16;
        asm volatile("st.shared.v4.b32 [%0], {%1,%2,%3,%4};" :: "r"(ah),
            "r"(hi[4*c]), "r"(hi[4*c+1]), "r"(hi[4*c+2]), "r"(hi[4*c+3]));
        asm volatile("st.shared.v4.b32 [%0], {%1,%2,%3,%4};" :: "r"(al),
            "r"(lo[4*c]), "r"(lo[4*c+1]), "r"(lo[4*c+2]), "r"(lo[4*c+3]));
    }
    return x16 * x16;   // q = x^32
}

__global__ __launch_bounds__(THREADS)
void poly_tc_kernel(const float* __restrict__ xg,
                    const float* __restrict__ wg,
                    float* __restrict__ out) {
    __shared__ __align__(128) unsigned char smW[32 * 128];
    __shared__ __align__(128) unsigned char smA[2][NWARP][32 * 128];

    const int tid  = threadIdx.x;
    const int wid  = tid >> 5;
    const int lane = tid & 31;
    const int g    = lane >> 2;
    const int cL   = lane & 3;

    const int warp_base = blockIdx.x * (NWARP * TILES_PER_WARP * 32)
                        + wid * (TILES_PER_WARP * 32);
    float x_next = xg[warp_base + lane];   // prefetch tile 0

    // ---- W_hi / W_lo tiles (once per block) ----
    for (int i = tid; i < 1024; i += THREADS) {
        float v = (i < NCOEF) ? wg[i] : 0.0f;
        __nv_bfloat16 hb = __float2bfloat16_rn(v);
        __nv_bfloat16 lb = __float2bfloat16_rn(v - __bfloat162float(hb));
        int n = i >> 5, k = i & 31;
        int ch = k >> 3, byo = (k & 7) * 2;
        *(__nv_bfloat16*)(smW + n * 128 + ((ch ^ (n & 7)) & 7) * 16 + byo) = hb;
        *(__nv_bfloat16*)(smW + n * 128 + (((ch + 4) ^ (n & 7)) & 7) * 16 + byo) = lb;
    }
    __syncthreads();

    // ---- persistent B fragments ----
    uint32_t bf[2][4][2][2];
    {
        const uint32_t wbase = cvta_s(smW);
        const int lr = lane & 15;
        #pragma unroll
        for (int part = 0; part < 2; part++)
            #pragma unroll
            for (int t = 0; t < 4; t++)
                #pragma unroll
                for (int h = 0; h < 2; h++) {
                    int row = 8 * t + (lr & 7);
                    int ch  = part * 4 + 2 * h + (lr >> 3);
                    uint32_t addr = wbase + row * 128 + ((ch ^ (row & 7)) & 7) * 16;
                    ldm_x2(bf[part][t][h][0], bf[part][t][h][1], addr);
                }
    }

    const uint32_t abase0 = cvta_s(smA[0][wid]);
    const uint32_t abase1 = cvta_s(smA[1][wid]);

    // Prologue: powers for tile 0 into buffer 0
    float q_cur = powers_store(x_next, abase0, lane);
    if (TILES_PER_WARP > 1) x_next = xg[warp_base + 32 + lane];

    #pragma unroll
    for (int tile = 0; tile < TILES_PER_WARP; tile++) {
        const uint32_t acur = (tile & 1) ? abase1 : abase0;
        __syncwarp();      // STS (this buffer) -> ldmatrix visibility

        // ---- A fragments for current tile ----
        uint32_t A[2][2][2][4];   // [m][part][h][4]
        #pragma unroll
        for (int m = 0; m < 2; m++)
            #pragma unroll
            for (int part = 0; part < 2; part++)
                #pragma unroll
                for (int h = 0; h < 2; h++) {
                    int row = 16 * m + (lane & 15);
                    int ch  = part * 4 + 2 * h + (lane >> 4);
                    uint32_t addr = acur + row * 128 + ((ch ^ (row & 7)) & 7) * 16;
                    ldm_x4(A[m][part][h][0], A[m][part][h][1],
                           A[m][part][h][2], A[m][part][h][3], addr);
                }

        // ---- pipeline: next tile's powers fill HMMA dependency gaps ----
        float q_next = 0.0f;
        if (tile + 1 < TILES_PER_WARP) {
            q_next = powers_store(x_next, (tile & 1) ? abase0 : abase1, lane);
            if (tile + 2 < TILES_PER_WARP)
                x_next = xg[warp_base + (tile + 2) * 32 + lane];
        }

        float yout = 0.0f;
        #pragma unroll
        for (int m = 0; m < 2; m++) {
            float D[4][4];
            #pragma unroll
            for (int t = 0; t < 4; t++) {
                mma16816_z(D[t], A[m][0][0], bf[0][t][0]);  // p_hi k0  x w_hi
                mma16816 (D[t], A[m][0][1], bf[0][t][1]);   // p_hi k16 x w_hi
                mma16816 (D[t], A[m][1][0], bf[0][t][0]);   // p_lo k0  x w_hi
                mma16816 (D[t], A[m][1][1], bf[0][t][1]);   // p_lo k16 x w_hi
                mma16816 (D[t], A[m][0][0], bf[1][t][0]);   // p_hi k0  x w_lo
                mma16816 (D[t], A[m][0][1], bf[1][t][1]);   // p_hi k16 x w_lo
            }

            float qe0 = __shfl_sync(0xffffffffu, q_cur, 16 * m + g);
            float qe1 = __shfl_sync(0xffffffffu, q_cur, 16 * m + g + 8);
            #pragma unroll
            for (int b = 0; b < 2; b++) {
                float qe  = b ? qe1 : qe0;
                float s0p = fmaf(qe, D[0][2*b+1], D[0][2*b]);
                float s1p = fmaf(qe, D[1][2*b+1], D[1][2*b]);
                float s2p = fmaf(qe, D[2][2*b+1], D[2][2*b]);
                float s3p = fmaf(qe, D[3][2*b+1], D[3][2*b]);
                float qe2 = qe * qe, qe4 = qe2 * qe2;
                float qe6 = qe4 * qe2, qe8 = qe4 * qe4;
                float P = fmaf(fmaf(fmaf(s3p, qe8, s2p), qe8, s1p), qe8, s0p);
                float qp = (cL == 0) ? 1.0f : (cL == 1) ? qe2
                         : (cL == 2) ? qe4 : qe6;
                float v = P * qp;
                v += __shfl_xor_sync(0xffffffffu, v, 1);
                v += __shfl_xor_sync(0xffffffffu, v, 2);
                if (((cL >> 1) == m) && ((cL & 1) == b)) yout = v;
            }
        }
        out[warp_base + tile * 32 + 16 * (cL >> 1) + g + 8 * (cL & 1)] = yout;
        q_cur = q_next;
    }
}

extern "C" void kernel_launch(void* const* d_in, const int* in_sizes, int n_in,
                              void* d_out, int out_size) {
    const float* x = (const float*)d_in[0];   // (512, 1024) fp32
    const float* w = (const float*)d_in[1];   // (1001,) fp32
    float* out = (float*)d_out;

    const int grid = out_size / (NWARP * TILES_PER_WARP * 32);   // 2048
    poly_tc_kernel<<<grid, THREADS>>>(x, w, out);
}

// round 10
// speedup vs baseline: 1.0313x; 1.0313x over previous
#include <cuda_runtime.h>
#include <cuda_bf16.h>
#include <cstdint>

#define THREADS 128
#define NWARP 4
#define TILES_PER_WARP 2
#define NCOEF 1001

__device__ __forceinline__ uint32_t cvta_s(const void* p) {
    return (uint32_t)__cvta_generic_to_shared(p);
}
__device__ __forceinline__ void ldm_x4(uint32_t& r0, uint32_t& r1,
                                       uint32_t& r2, uint32_t& r3, uint32_t addr) {
    asm volatile("ldmatrix.sync.aligned.m8n8.x4.shared.b16 {%0,%1,%2,%3}, [%4];"
                 : "=r"(r0), "=r"(r1), "=r"(r2), "=r"(r3) : "r"(addr));
}
__device__ __forceinline__ void ldm_x2(uint32_t& r0, uint32_t& r1, uint32_t addr) {
    asm volatile("ldmatrix.sync.aligned.m8n8.x2.shared.b16 {%0,%1}, [%2];"
                 : "=r"(r0), "=r"(r1) : "r"(addr));
}
__device__ __forceinline__ void mma16816(float* d, const uint32_t* a,
                                         const uint32_t* b) {
    asm volatile("mma.sync.aligned.m16n8k16.row.col.f32.bf16.bf16.f32 "
                 "{%0,%1,%2,%3}, {%4,%5,%6,%7}, {%8,%9}, {%0,%1,%2,%3};"
                 : "+f"(d[0]), "+f"(d[1]), "+f"(d[2]), "+f"(d[3])
                 : "r"(a[0]), "r"(a[1]), "r"(a[2]), "r"(a[3]),
                   "r"(b[0]), "r"(b[1]));
}
__device__ __forceinline__ void mma16816_z(float* d, const uint32_t* a,
                                           const uint32_t* b) {
    asm volatile("mma.sync.aligned.m16n8k16.row.col.f32.bf16.bf16.f32 "
                 "{%0,%1,%2,%3}, {%4,%5,%6,%7}, {%8,%9}, {%10,%10,%10,%10};"
                 : "=f"(d[0]), "=f"(d[1]), "=f"(d[2]), "=f"(d[3])
                 : "r"(a[0]), "r"(a[1]), "r"(a[2]), "r"(a[3]),
                   "r"(b[0]), "r"(b[1]), "f"(0.0f));
}

// All tiles: rows of 128B (8 chunks of 16B), XOR swizzle:
//   addr(row, ch) = base + row*128 + ((ch ^ (row&7)) & 7)*16

// x^0..x^31 (power-of-2 factor tree), bf16 hi/lo split, stored to A tile.
// Returns q = x^32.
__device__ __forceinline__ float powers_store(float x, uint32_t abuf, int lane) {
    float x2 = x * x, x4 = x2 * x2, x8 = x4 * x4, x16 = x8 * x8;
    float e[16];
    e[0] = 1.0f;       e[1] = x2;          e[2] = x4;          e[3] = x4 * x2;
    e[4] = x8;         e[5] = x8 * x2;     e[6] = x8 * x4;     e[7] = e[6] * x2;
    e[8] = x16;        e[9] = x16 * x2;    e[10] = x16 * x4;   e[11] = e[10] * x2;
    e[12] = x16 * x8;  e[13] = e[12] * x2; e[14] = e[12] * x4; e[15] = e[14] * x2;

    uint32_t hi[16], lo[16];
    #pragma unroll
    for (int i = 0; i < 16; i++) {
        float p0 = e[i], p1 = e[i] * x;
        __nv_bfloat162 h2 = __floats2bfloat162_rn(p0, p1);    // low = p0
        uint32_t hb = *reinterpret_cast<uint32_t*>(&h2);
        float h0 = __uint_as_float(hb << 16);
        float h1 = __uint_as_float(hb & 0xFFFF0000u);
        __nv_bfloat162 l2 = __floats2bfloat162_rn(p0 - h0, p1 - h1);
        hi[i] = hb;
        lo[i] = *reinterpret_cast<uint32_t*>(&l2);
    }
    #pragma unroll
    for (int c = 0; c < 4; c++) {
        uint32_t ah = abuf + lane * 128 + ((c ^ (lane & 7)) & 7) * 16;
        uint32_t al = abuf + lane * 128 + (((c + 4) ^ (lane & 7)) & 7) * 16;
        asm volatile("st.shared.v4.b32 [%0], {%1,%2,%3,%4};" :: "r"(ah),
            "r"(hi[4*c]), "r"(hi[4*c+1]), "r"(hi[4*c+2]), "r"(hi[4*c+3]));
        asm volatile("st.shared.v4.b32 [%0], {%1,%2,%3,%4};" :: "r"(al),
            "r"(lo[4*c]), "r"(lo[4*c+1]), "r"(lo[4*c+2]), "r"(lo[4*c+3]));
    }
    return x16 * x16;
}

__device__ __forceinline__ float horner8(float4 a, float4 b, float q) {
    float h = b.w;
    h = fmaf(h, q, b.z); h = fmaf(h, q, b.y); h = fmaf(h, q, b.x);
    h = fmaf(h, q, a.w); h = fmaf(h, q, a.z); h = fmaf(h, q, a.y);
    return fmaf(h, q, a.x);
}

__global__ __launch_bounds__(THREADS)
void poly_tc_kernel(const float* __restrict__ xg,
                    const float* __restrict__ wg,
                    float* __restrict__ out) {
    __shared__ __align__(128) unsigned char smW[32 * 128];
    __shared__ __align__(128) unsigned char smA[NWARP][32 * 128];

    const int tid  = threadIdx.x;
    const int wid  = tid >> 5;
    const int lane = tid & 31;
    const int g    = lane >> 2;   // mma groupID
    const int cL   = lane & 3;    // mma thread-in-group

    const int warp_base = blockIdx.x * (NWARP * TILES_PER_WARP * 32)
                        + wid * (TILES_PER_WARP * 32);
    float x0 = xg[warp_base + lane];          // both tiles' x in flight early
    float x1 = xg[warp_base + 32 + lane];

    // ---- W_hi / W_lo tiles (once per block) ----
    for (int i = tid; i < 1024; i += THREADS) {
        float v = (i < NCOEF) ? wg[i] : 0.0f;
        __nv_bfloat16 hb = __float2bfloat16_rn(v);
        __nv_bfloat16 lb = __float2bfloat16_rn(v - __bfloat162float(hb));
        int n = i >> 5, k = i & 31;
        int ch = k >> 3, byo = (k & 7) * 2;
        *(__nv_bfloat16*)(smW + n * 128 + ((ch ^ (n & 7)) & 7) * 16 + byo) = hb;
        *(__nv_bfloat16*)(smW + n * 128 + (((ch + 4) ^ (n & 7)) & 7) * 16 + byo) = lb;
    }
    __syncthreads();

    // ---- persistent B fragments: bf[part][t][h][2] ----
    uint32_t bf[2][4][2][2];
    {
        const uint32_t wbase = cvta_s(smW);
        const int lr = lane & 15;
        #pragma unroll
        for (int part = 0; part < 2; part++)
            #pragma unroll
            for (int t = 0; t < 4; t++)
                #pragma unroll
                for (int h = 0; h < 2; h++) {
                    int row = 8 * t + (lr & 7);
                    int ch  = part * 4 + 2 * h + (lr >> 3);
                    uint32_t addr = wbase + row * 128 + ((ch ^ (row & 7)) & 7) * 16;
                    ldm_x2(bf[part][t][h][0], bf[part][t][h][1], addr);
                }
    }

    const uint32_t abase = cvta_s(smA[wid]);

    #pragma unroll
    for (int tile = 0; tile < TILES_PER_WARP; tile++) {
        __syncwarp();   // prior tile's S reads done before overwriting A tile
        const float q = powers_store(tile ? x1 : x0, abase, lane);
        __syncwarp();   // powers visible to ldmatrix

        #pragma unroll
        for (int m = 0; m < 2; m++) {
            // A fragments for this m only (16 regs live)
            uint32_t A[2][2][4];   // [part][h][4]
            #pragma unroll
            for (int part = 0; part < 2; part++)
                #pragma unroll
                for (int h = 0; h < 2; h++) {
                    int row = 16 * m + (lane & 15);
                    int ch  = part * 4 + 2 * h + (lane >> 4);
                    uint32_t addr = abase + row * 128 + ((ch ^ (row & 7)) & 7) * 16;
                    ldm_x4(A[part][h][0], A[part][h][1],
                           A[part][h][2], A[part][h][3], addr);
                }

            float D[4][4];
            #pragma unroll
            for (int t = 0; t < 4; t++) {
                mma16816_z(D[t], A[0][0], bf[0][t][0]);
                mma16816 (D[t], A[0][1], bf[0][t][1]);
                mma16816 (D[t], A[1][0], bf[0][t][0]);
                mma16816 (D[t], A[1][1], bf[0][t][1]);
                mma16816 (D[t], A[0][0], bf[1][t][0]);
                mma16816 (D[t], A[0][1], bf[1][t][1]);
            }

            // Store S_j back into the (consumed) A tile, swizzled fp32 rows:
            // S[elem][j]: elem rows 16m+g / 16m+g+8, j = 8t+2cL (+1).
            // WAR on A rows is safe: D depends on this m's ldmatrix;
            // m=0 writes rows 0..15, m=1's A reads rows 16..31 (disjoint).
            #pragma unroll
            for (int t = 0; t < 4; t++) {
                int ch  = 2 * t + (cL >> 1);
                int sub = 8 * (cL & 1);
                int r0  = 16 * m + g;
                int r1  = r0 + 8;
                uint32_t a0 = abase + r0 * 128 + ((ch ^ (r0 & 7)) & 7) * 16 + sub;
                uint32_t a1 = abase + r1 * 128 + ((ch ^ (r1 & 7)) & 7) * 16 + sub;
                asm volatile("st.shared.v2.b32 [%0], {%1,%2};"
                             :: "r"(a0), "f"(D[t][0]), "f"(D[t][1]));
                asm volatile("st.shared.v2.b32 [%0], {%1,%2};"
                             :: "r"(a1), "f"(D[t][2]), "f"(D[t][3]));
            }
        }
        __syncwarp();   // S complete before readback

        // Per-element epilogue: lane reads its own 32 S values, Horner in q.
        float4 s[8];
        #pragma unroll
        for (int ch = 0; ch < 8; ch++) {
            uint32_t addr = abase + lane * 128 + ((ch ^ (lane & 7)) & 7) * 16;
            asm volatile("ld.shared.v4.f32 {%0,%1,%2,%3}, [%4];"
                         : "=f"(s[ch].x), "=f"(s[ch].y),
                           "=f"(s[ch].z), "=f"(s[ch].w) : "r"(addr));
        }
        float q2 = q * q, q4 = q2 * q2, q8 = q4 * q4;
        float C0 = horner8(s[0], s[1], q);
        float C1 = horner8(s[2], s[3], q);
        float C2 = horner8(s[4], s[5], q);
        float C3 = horner8(s[6], s[7], q);
        float y = fmaf(fmaf(fmaf(C3, q8, C2), q8, C1), q8, C0);
        out[warp_base + tile * 32 + lane] = y;
    }
}

extern "C" void kernel_launch(void* const* d_in, const int* in_sizes, int n_in,
                              void* d_out, int out_size) {
    const float* x = (const float*)d_in[0];   // (512, 1024) fp32
    const float* w = (const float*)d_in[1];   // (1001,) fp32
    float* out = (float*)d_out;

    const int grid = out_size / (NWARP * TILES_PER_WARP * 32);   // 2048
    poly_tc_kernel<<<grid, THREADS>>>(x, w, out);
}